// round 4
// baseline (speedup 1.0000x reference)
#include <cuda_runtime.h>
#include <math.h>

#define NNODES 30000
#define DIM    128
#define TLINKS 3000
#define KNEG   75
#define GAMMA  1.0f
#define MAXSQ  50.0f
// float(1.0 + 1e-7) == 0x3F800001 (1 ulp above 1.0f) — matches XLA's f32 cast
#define THETA0 (1.0f + 1e-7f)

// ---- device scratch (no allocation allowed) ----
__device__ double g_acc;
__device__ int    g_is64;   // train_links dtype: 1 = int64, 0 = int32

// ---------------------------------------------------------------------------
__device__ __forceinline__ long long get_link(const void* links, int pos) {
    return g_is64 ? ((const long long*)links)[pos]
                  : (long long)((const int*)links)[pos];
}

__device__ __forceinline__ float sqdist_from_mdot(float mdot, float cval, float Kv) {
    float th = fmaxf(-mdot * cval, THETA0);
    float a  = acoshf(th);
    return fminf(Kv * a * a, MAXSQ);
}

// full 128-dim Minkowski sqdist, one thread (fallback path only)
__device__ __forceinline__ float sqdist_full(const float* __restrict__ q,
                                             const float* __restrict__ row,
                                             float cval, float Kv) {
    float md = 0.f;
#pragma unroll
    for (int d = 0; d < DIM; d++) {
        float p = q[d] * row[d];
        md += (d == 0) ? -p : p;
    }
    return sqdist_from_mdot(md, cval, Kv);
}

// ---------------------------------------------------------------------------
// setup: detect int64-vs-int32 links (int64 values < 30000 -> odd words 0),
// and zero the global accumulator (graph replays re-run this each time).
__global__ void setup_kernel(const int* __restrict__ links32) {
    int bad = 0;
    for (int i = threadIdx.x; i < TLINKS; i += blockDim.x)
        if (links32[2 * i + 1] != 0) bad = 1;
    int any = __syncthreads_or(bad);
    if (threadIdx.x == 0) { g_is64 = any ? 0 : 1; g_acc = 0.0; }
}

// ---------------------------------------------------------------------------
// Exact fallback (essentially never taken; kept for correctness): block-wide
// MSB-first radix select of the 75th smallest sqdist tau over all 30000
// candidates, then sum relu(D - v) over values < tau plus ties at tau.
// Result valid on tid 0.
__device__ double fallback_query(const float* __restrict__ q,
                                 const float* __restrict__ emb,
                                 float cval, float Kv, float D,
                                 unsigned int* hist, unsigned int* s_prefix,
                                 int* s_k, double* ssum, int* scm) {
    const int tid = threadIdx.x;
    if (tid == 0) { *s_prefix = 0u; *s_k = KNEG; }
    __syncthreads();

    for (int pass = 0; pass < 4; pass++) {
        const int shift = 24 - 8 * pass;
        const unsigned int pmask  = (pass == 0) ? 0u : (0xFFFFFFFFu << (shift + 8));
        const unsigned int prefix = *s_prefix;
        hist[tid] = 0u;
        __syncthreads();
        for (int j = tid; j < NNODES; j += 256) {
            float v = sqdist_full(q, emb + (size_t)j * DIM, cval, Kv);
            unsigned int b = __float_as_uint(v);
            if ((b & pmask) == prefix)
                atomicAdd(&hist[(b >> shift) & 0xFFu], 1u);
        }
        __syncthreads();
        if (tid == 0) {
            int k = *s_k;
            unsigned int acc = 0;
            int digit = 0;
            for (; digit < 255; digit++) {
                if (acc + hist[digit] >= (unsigned)k) break;
                acc += hist[digit];
            }
            *s_k      = k - (int)acc;
            *s_prefix = prefix | ((unsigned)digit << shift);
        }
        __syncthreads();
    }

    const unsigned int tau_bits = *s_prefix;
    const float        tau      = __uint_as_float(tau_bits);

    int    m_local = 0;
    double sum_local = 0.0;
    for (int j = tid; j < NNODES; j += 256) {
        float v = sqdist_full(q, emb + (size_t)j * DIM, cval, Kv);
        if (__float_as_uint(v) < tau_bits) {
            m_local++;
            sum_local += (double)fmaxf(D - v, 0.f);
        }
    }
    ssum[tid] = sum_local;
    scm[tid]  = m_local;
    __syncthreads();
    for (int o = 128; o > 0; o >>= 1) {
        if (tid < o) { ssum[tid] += ssum[tid + o]; scm[tid] += scm[tid + o]; }
        __syncthreads();
    }
    double res = 0.0;
    if (tid == 0) {
        int m = scm[0];
        res = ssum[0] + (double)(KNEG - m) * (double)fmaxf(D - tau, 0.f);
    }
    __syncthreads();
    return res;
}

// ---------------------------------------------------------------------------
// Main kernel: one block (256 threads) per link.
//  - stage both query rows in shared, keep each lane's 16-dim slice in regs
//    (Minkowski sign folded into the register copy)
//  - D computed by warp 0 (3-step 8-lane butterfly)
//  - candidate scan: 8-lane sub-groups each own one row; warp covers 4 rows
//    per group-iter, both queries per pass; count rows with theta clipped
//    (mdot >= -THETA0/c  <=>  sqdist == S0 == global minimum).
//  - once count >= 75 for a query, its top-75 are all exactly S0 and the
//    contribution is 75 * relu(D - S0); else exact radix fallback.
__global__ void __launch_bounds__(256) main_kernel(const float* __restrict__ emb,
                                                   const float* __restrict__ cptr,
                                                   const void*  __restrict__ links) {
    __shared__ float        q[2][DIM];
    __shared__ float        sD;
    __shared__ int          sc0, sc1;
    __shared__ unsigned int hist[256];
    __shared__ unsigned int s_prefix;
    __shared__ int          s_k;
    __shared__ double       ssum[256];
    __shared__ int          scm[256];

    const int t    = blockIdx.x;
    const int tid  = threadIdx.x;
    const int w    = tid >> 5;
    const int lane = tid & 31;
    const int sub  = lane & 7;          // 8-lane sub-group position

    const float cval = cptr[0];
    const float Kv   = 1.0f / cval;

    const long long L = get_link(links, 2 * t);
    const long long R = get_link(links, 2 * t + 1);
    if (tid < 128) q[0][tid]       = emb[(size_t)L * DIM + tid];
    else           q[1][tid - 128] = emb[(size_t)R * DIM + (tid - 128)];
    if (tid == 0) { sc0 = 0; sc1 = 0; }
    __syncthreads();

    // per-lane 16-dim register slices of both queries, dim-0 sign folded in
    float4 a0[4], a1[4];
#pragma unroll
    for (int i = 0; i < 4; i++) {
        a0[i] = *(const float4*)&q[0][sub * 16 + i * 4];
        a1[i] = *(const float4*)&q[1][sub * 16 + i * 4];
    }
    if (sub == 0) { a0[0].x = -a0[0].x; a1[0].x = -a1[0].x; }

    // D = sqdist(left,right) + GAMMA  (sign-folded a0 vs RAW q1)
    if (w == 0) {
        float s = 0.f;
#pragma unroll
        for (int i = 0; i < 4; i++) {
            float4 b = *(const float4*)&q[1][sub * 16 + i * 4];
            s += a0[i].x * b.x + a0[i].y * b.y + a0[i].z * b.z + a0[i].w * b.w;
        }
        s += __shfl_xor_sync(0xffffffffu, s, 1);
        s += __shfl_xor_sync(0xffffffffu, s, 2);
        s += __shfl_xor_sync(0xffffffffu, s, 4);
        if (tid == 0) sD = sqdist_from_mdot(s, cval, Kv) + GAMMA;
    }
    __syncthreads();
    const float D = sD;

    float acz = acoshf(THETA0);
    const float S0  = fminf(Kv * acz * acz, MAXSQ);
    const float thr = -(THETA0 * Kv);    // mdot >= thr  <=>  theta clips to 1+EPS

    int c0 = 0, c1 = 0;
    int base = 0;
    while (base < NNODES && (c0 < KNEG || c1 < KNEG)) {
        const int rbase = base + (w << 5) + (lane >> 3);
        int l0 = 0, l1 = 0;
#pragma unroll 2
        for (int g = 0; g < 8; g++) {
            int row = rbase + g * 4;
            float s0 = -1e30f, s1 = -1e30f;
            if (row < NNODES) {
                const float4* p = (const float4*)(emb + (size_t)row * DIM + sub * 16);
                s0 = 0.f; s1 = 0.f;
#pragma unroll
                for (int i = 0; i < 4; i++) {
                    float4 y = p[i];
                    s0 += a0[i].x * y.x + a0[i].y * y.y + a0[i].z * y.z + a0[i].w * y.w;
                    s1 += a1[i].x * y.x + a1[i].y * y.y + a1[i].z * y.z + a1[i].w * y.w;
                }
            }
            // 3-step butterfly within the 8-lane sub-group (both queries)
            s0 += __shfl_xor_sync(0xffffffffu, s0, 1);
            s1 += __shfl_xor_sync(0xffffffffu, s1, 1);
            s0 += __shfl_xor_sync(0xffffffffu, s0, 2);
            s1 += __shfl_xor_sync(0xffffffffu, s1, 2);
            s0 += __shfl_xor_sync(0xffffffffu, s0, 4);
            s1 += __shfl_xor_sync(0xffffffffu, s1, 4);
            l0 += (s0 >= thr);
            l1 += (s1 >= thr);
        }
        // combine the 4 sub-group counts (each replicated over 8 lanes)
        l0 += __shfl_xor_sync(0xffffffffu, l0, 8);
        l1 += __shfl_xor_sync(0xffffffffu, l1, 8);
        l0 += __shfl_xor_sync(0xffffffffu, l0, 16);
        l1 += __shfl_xor_sync(0xffffffffu, l1, 16);
        l0 >>= 3; l1 >>= 3;              // each row counted by 8 lanes
        if (lane == 0) { atomicAdd(&sc0, l0); atomicAdd(&sc1, l1); }
        __syncthreads();
        c0 = sc0; c1 = sc1;
        base += 256;
        if (base < NNODES && (c0 < KNEG || c1 < KNEG)) __syncthreads();
    }

    double contrib = 0.0;
    if (c0 >= KNEG) {
        if (tid == 0) contrib += (double)KNEG * (double)fmaxf(D - S0, 0.f);
    } else {
        double r = fallback_query(q[0], emb, cval, Kv, D, hist, &s_prefix, &s_k, ssum, scm);
        if (tid == 0) contrib += r;
    }
    if (c1 >= KNEG) {
        if (tid == 0) contrib += (double)KNEG * (double)fmaxf(D - S0, 0.f);
    } else {
        double r = fallback_query(q[1], emb, cval, Kv, D, hist, &s_prefix, &s_k, ssum, scm);
        if (tid == 0) contrib += r;
    }

    if (tid == 0) atomicAdd(&g_acc, contrib);
}

// ---------------------------------------------------------------------------
__global__ void finish_kernel(float* __restrict__ out) {
    out[0] = (float)(g_acc / (2.0 * (double)KNEG * (double)TLINKS));
}

// ---------------------------------------------------------------------------
extern "C" void kernel_launch(void* const* d_in, const int* in_sizes, int n_in,
                              void* d_out, int out_size) {
    const float* emb   = nullptr;
    const float* c     = nullptr;
    const void*  links = nullptr;
    for (int i = 0; i < n_in; i++) {
        if (in_sizes[i] == 1)               c     = (const float*)d_in[i];
        else if (in_sizes[i] == 2 * TLINKS) links = d_in[i];
        else                                emb   = (const float*)d_in[i];
    }

    setup_kernel <<<1, 256>>>((const int*)links);
    main_kernel  <<<TLINKS, 256>>>(emb, c, links);
    finish_kernel<<<1, 1>>>((float*)d_out);
}

// round 5
// speedup vs baseline: 4.3018x; 4.3018x over previous
#include <cuda_runtime.h>
#include <math.h>

#define NNODES 30000
#define DIM    128
#define TLINKS 3000
#define KNEG   75
#define GAMMA  1.0f
#define MAXSQ  50.0f
// float(1.0 + 1e-7) == 0x3F800001 (1 ulp above 1.0f) — matches XLA's f32 cast
#define THETA0 (1.0f + 1e-7f)

// ---- device scratch (no allocation allowed) ----
__device__ double g_acc;
__device__ int    g_is64;   // train_links dtype: 1 = int64, 0 = int32

// ---------------------------------------------------------------------------
__device__ __forceinline__ long long get_link(const void* links, int pos) {
    return g_is64 ? ((const long long*)links)[pos]
                  : (long long)((const int*)links)[pos];
}

__device__ __forceinline__ float sqdist_from_mdot(float mdot, float cval, float Kv) {
    float th = fmaxf(-mdot * cval, THETA0);
    float a  = acoshf(th);
    return fminf(Kv * a * a, MAXSQ);
}

// full 128-dim Minkowski sqdist, one thread (fallback path only)
__device__ __forceinline__ float sqdist_full(const float* __restrict__ q,
                                             const float* __restrict__ row,
                                             float cval, float Kv) {
    float md = 0.f;
#pragma unroll
    for (int d = 0; d < DIM; d++) {
        float p = q[d] * row[d];
        md += (d == 0) ? -p : p;
    }
    return sqdist_from_mdot(md, cval, Kv);
}

// ---------------------------------------------------------------------------
// setup: detect int64-vs-int32 links (int64 values < 30000 -> odd words 0),
// and zero the global accumulator (graph replays re-run this each time).
__global__ void setup_kernel(const int* __restrict__ links32) {
    int bad = 0;
    for (int i = threadIdx.x; i < TLINKS; i += blockDim.x)
        if (links32[2 * i + 1] != 0) bad = 1;
    int any = __syncthreads_or(bad);
    if (threadIdx.x == 0) { g_is64 = any ? 0 : 1; g_acc = 0.0; }
}

// ---------------------------------------------------------------------------
// Exact fallback (essentially never taken; kept for correctness): block-wide
// MSB-first radix select of the 75th smallest sqdist tau over all 30000
// candidates, then sum relu(D - v) over values < tau plus ties at tau.
// Result valid on tid 0.
__device__ double fallback_query(const float* __restrict__ q,
                                 const float* __restrict__ emb,
                                 float cval, float Kv, float D,
                                 unsigned int* hist, unsigned int* s_prefix,
                                 int* s_k, double* ssum, int* scm) {
    const int tid = threadIdx.x;
    if (tid == 0) { *s_prefix = 0u; *s_k = KNEG; }
    __syncthreads();

    for (int pass = 0; pass < 4; pass++) {
        const int shift = 24 - 8 * pass;
        const unsigned int pmask  = (pass == 0) ? 0u : (0xFFFFFFFFu << (shift + 8));
        const unsigned int prefix = *s_prefix;
        hist[tid] = 0u;
        __syncthreads();
        for (int j = tid; j < NNODES; j += 256) {
            float v = sqdist_full(q, emb + (size_t)j * DIM, cval, Kv);
            unsigned int b = __float_as_uint(v);
            if ((b & pmask) == prefix)
                atomicAdd(&hist[(b >> shift) & 0xFFu], 1u);
        }
        __syncthreads();
        if (tid == 0) {
            int k = *s_k;
            unsigned int acc = 0;
            int digit = 0;
            for (; digit < 255; digit++) {
                if (acc + hist[digit] >= (unsigned)k) break;
                acc += hist[digit];
            }
            *s_k      = k - (int)acc;
            *s_prefix = prefix | ((unsigned)digit << shift);
        }
        __syncthreads();
    }

    const unsigned int tau_bits = *s_prefix;
    const float        tau      = __uint_as_float(tau_bits);

    int    m_local = 0;
    double sum_local = 0.0;
    for (int j = tid; j < NNODES; j += 256) {
        float v = sqdist_full(q, emb + (size_t)j * DIM, cval, Kv);
        if (__float_as_uint(v) < tau_bits) {
            m_local++;
            sum_local += (double)fmaxf(D - v, 0.f);
        }
    }
    ssum[tid] = sum_local;
    scm[tid]  = m_local;
    __syncthreads();
    for (int o = 128; o > 0; o >>= 1) {
        if (tid < o) { ssum[tid] += ssum[tid + o]; scm[tid] += scm[tid + o]; }
        __syncthreads();
    }
    double res = 0.0;
    if (tid == 0) {
        int m = scm[0];
        res = ssum[0] + (double)(KNEG - m) * (double)fmaxf(D - tau, 0.f);
    }
    __syncthreads();
    return res;
}

// ---------------------------------------------------------------------------
// Main kernel: one block (256 threads) per link.
//  - stage both query rows in shared, keep each lane's 16-dim slice in regs
//    (Minkowski sign folded into the register copy)
//  - D computed by warp 0 (3-step 8-lane butterfly)
//  - candidate scan: 8-lane sub-groups each own one row; warp covers 4 rows
//    per group-iter, both queries per pass; count rows with theta clipped
//    (mdot >= -THETA0/c  <=>  sqdist == S0 == global minimum).
//  - once count >= 75 for a query, its top-75 are all exactly S0 and the
//    contribution is 75 * relu(D - S0); else exact radix fallback.
__global__ void __launch_bounds__(256) main_kernel(const float* __restrict__ emb,
                                                   const float* __restrict__ cptr,
                                                   const void*  __restrict__ links) {
    __shared__ float        q[2][DIM];
    __shared__ float        sD;
    __shared__ int          sc0, sc1;
    __shared__ unsigned int hist[256];
    __shared__ unsigned int s_prefix;
    __shared__ int          s_k;
    __shared__ double       ssum[256];
    __shared__ int          scm[256];

    const int t    = blockIdx.x;
    const int tid  = threadIdx.x;
    const int w    = tid >> 5;
    const int lane = tid & 31;
    const int sub  = lane & 7;          // 8-lane sub-group position

    const float cval = cptr[0];
    const float Kv   = 1.0f / cval;

    const long long L = get_link(links, 2 * t);
    const long long R = get_link(links, 2 * t + 1);
    if (tid < 128) q[0][tid]       = emb[(size_t)L * DIM + tid];
    else           q[1][tid - 128] = emb[(size_t)R * DIM + (tid - 128)];
    if (tid == 0) { sc0 = 0; sc1 = 0; }
    __syncthreads();

    // per-lane 16-dim register slices of both queries, dim-0 sign folded in
    float4 a0[4], a1[4];
#pragma unroll
    for (int i = 0; i < 4; i++) {
        a0[i] = *(const float4*)&q[0][sub * 16 + i * 4];
        a1[i] = *(const float4*)&q[1][sub * 16 + i * 4];
    }
    if (sub == 0) { a0[0].x = -a0[0].x; a1[0].x = -a1[0].x; }

    // D = sqdist(left,right) + GAMMA  (sign-folded a0 vs RAW q1)
    if (w == 0) {
        float s = 0.f;
#pragma unroll
        for (int i = 0; i < 4; i++) {
            float4 b = *(const float4*)&q[1][sub * 16 + i * 4];
            s += a0[i].x * b.x + a0[i].y * b.y + a0[i].z * b.z + a0[i].w * b.w;
        }
        s += __shfl_xor_sync(0xffffffffu, s, 1);
        s += __shfl_xor_sync(0xffffffffu, s, 2);
        s += __shfl_xor_sync(0xffffffffu, s, 4);
        if (tid == 0) sD = sqdist_from_mdot(s, cval, Kv) + GAMMA;
    }
    __syncthreads();
    const float D = sD;

    float acz = acoshf(THETA0);
    const float S0  = fminf(Kv * acz * acz, MAXSQ);
    const float thr = -(THETA0 * Kv);    // mdot >= thr  <=>  theta clips to 1+EPS

    int c0 = 0, c1 = 0;
    int base = 0;
    while (base < NNODES && (c0 < KNEG || c1 < KNEG)) {
        const int rbase = base + (w << 5) + (lane >> 3);
        int l0 = 0, l1 = 0;
#pragma unroll 2
        for (int g = 0; g < 8; g++) {
            int row = rbase + g * 4;
            float s0 = -1e30f, s1 = -1e30f;
            if (row < NNODES) {
                const float4* p = (const float4*)(emb + (size_t)row * DIM + sub * 16);
                s0 = 0.f; s1 = 0.f;
#pragma unroll
                for (int i = 0; i < 4; i++) {
                    float4 y = p[i];
                    s0 += a0[i].x * y.x + a0[i].y * y.y + a0[i].z * y.z + a0[i].w * y.w;
                    s1 += a1[i].x * y.x + a1[i].y * y.y + a1[i].z * y.z + a1[i].w * y.w;
                }
            }
            // 3-step butterfly within the 8-lane sub-group (both queries)
            s0 += __shfl_xor_sync(0xffffffffu, s0, 1);
            s1 += __shfl_xor_sync(0xffffffffu, s1, 1);
            s0 += __shfl_xor_sync(0xffffffffu, s0, 2);
            s1 += __shfl_xor_sync(0xffffffffu, s1, 2);
            s0 += __shfl_xor_sync(0xffffffffu, s0, 4);
            s1 += __shfl_xor_sync(0xffffffffu, s1, 4);
            // s0/s1 replicated across the 8 lanes of the sub-group; each
            // lane's l0 = count over its sub-group's rows (once per row)
            l0 += (s0 >= thr);
            l1 += (s1 >= thr);
        }
        // combine the 4 sub-group counts: lanes 0-7 hold subgroup0's count,
        // 8-15 subgroup1's, etc. xor8+xor16 -> every lane holds the exact
        // warp count of its 32 rows (NO division needed).
        l0 += __shfl_xor_sync(0xffffffffu, l0, 8);
        l1 += __shfl_xor_sync(0xffffffffu, l1, 8);
        l0 += __shfl_xor_sync(0xffffffffu, l0, 16);
        l1 += __shfl_xor_sync(0xffffffffu, l1, 16);
        if (lane == 0) { atomicAdd(&sc0, l0); atomicAdd(&sc1, l1); }
        __syncthreads();
        c0 = sc0; c1 = sc1;
        __syncthreads();
        base += 256;
    }

    double contrib = 0.0;
    if (c0 >= KNEG) {
        if (tid == 0) contrib += (double)KNEG * (double)fmaxf(D - S0, 0.f);
    } else {
        double r = fallback_query(q[0], emb, cval, Kv, D, hist, &s_prefix, &s_k, ssum, scm);
        if (tid == 0) contrib += r;
    }
    if (c1 >= KNEG) {
        if (tid == 0) contrib += (double)KNEG * (double)fmaxf(D - S0, 0.f);
    } else {
        double r = fallback_query(q[1], emb, cval, Kv, D, hist, &s_prefix, &s_k, ssum, scm);
        if (tid == 0) contrib += r;
    }

    if (tid == 0) atomicAdd(&g_acc, contrib);
}

// ---------------------------------------------------------------------------
__global__ void finish_kernel(float* __restrict__ out) {
    out[0] = (float)(g_acc / (2.0 * (double)KNEG * (double)TLINKS));
}

// ---------------------------------------------------------------------------
extern "C" void kernel_launch(void* const* d_in, const int* in_sizes, int n_in,
                              void* d_out, int out_size) {
    const float* emb   = nullptr;
    const float* c     = nullptr;
    const void*  links = nullptr;
    for (int i = 0; i < n_in; i++) {
        if (in_sizes[i] == 1)               c     = (const float*)d_in[i];
        else if (in_sizes[i] == 2 * TLINKS) links = d_in[i];
        else                                emb   = (const float*)d_in[i];
    }

    setup_kernel <<<1, 256>>>((const int*)links);
    main_kernel  <<<TLINKS, 256>>>(emb, c, links);
    finish_kernel<<<1, 1>>>((float*)d_out);
}